// round 2
// baseline (speedup 1.0000x reference)
#include <cuda_runtime.h>

#define BATCH 4096
#define S_SZ  200
#define S_PAD 208           // 13 m-tiles of 16
#define D_SZ  256
#define LDW   132           // words per row (128 data + 4 pad) -> conflict-free frags

__device__ float g_catep[BATCH * D_SZ];
__device__ int   g_mask_mode;   // 0 = uint8, 1 = int32, 2 = float32

__device__ __forceinline__ unsigned pack_bf2(float lo, float hi) {
    unsigned r;
    asm("cvt.rn.bf16x2.f32 %0, %1, %2;" : "=r"(r) : "f"(hi), "f"(lo));
    return r;
}
__device__ __forceinline__ float bf_lo(unsigned w) { return __uint_as_float(w << 16); }
__device__ __forceinline__ float bf_hi(unsigned w) { return __uint_as_float(w & 0xFFFF0000u); }
__device__ __forceinline__ float sigf(float x) { return 1.0f / (1.0f + __expf(-x)); }

#define MMA16816(d, a0, a1, a2, a3, b0, b1)                                   \
    asm volatile("mma.sync.aligned.m16n8k16.row.col.f32.bf16.bf16.f32 "       \
                 "{%0,%1,%2,%3}, {%4,%5,%6,%7}, {%8,%9}, {%0,%1,%2,%3};"      \
                 : "+f"(d[0]), "+f"(d[1]), "+f"(d[2]), "+f"(d[3])             \
                 : "r"(a0), "r"(a1), "r"(a2), "r"(a3), "r"(b0), "r"(b1))

// ---------------------------------------------------------------------------
// Mask dtype detection: bool may arrive as u8, i32 or f32. Deterministic.
// ---------------------------------------------------------------------------
__global__ void detect_mask_kernel(const unsigned* __restrict__ mw) {
    if (threadIdx.x == 0) {
        int mode = 1;                                // default: int32 (words 0/1)
        for (int i = 0; i < 512; i++) {
            unsigned v = mw[i];
            if (v == 0x3F800000u) { mode = 2; break; }          // float 1.0f
            if ((v & 0xFFFFFF00u) != 0u) { mode = 0; break; }   // bytes 1..3 set -> u8
        }
        g_mask_mode = mode;
    }
}

// ---------------------------------------------------------------------------
// cate_p[b,e] = dot(cate[b,:], W2[e,:]) + b2[e]   (fp32 exact)
// ---------------------------------------------------------------------------
__global__ void catep_kernel(const float* __restrict__ cate,
                             const float* __restrict__ W2,
                             const float* __restrict__ b2) {
    __shared__ float sm[16 * 256];
    const int bbase = blockIdx.x * 16;
    const int tid = threadIdx.x;

    #pragma unroll
    for (int i = 0; i < 16; i++)
        sm[i * 256 + tid] = cate[(size_t)(bbase + i) * 256 + tid];
    __syncthreads();

    float acc[16];
    #pragma unroll
    for (int r = 0; r < 16; r++) acc[r] = 0.0f;

    const float* w2row = W2 + (size_t)tid * 256;
    #pragma unroll 4
    for (int k = 0; k < 256; k++) {
        const float w = w2row[k];
        #pragma unroll
        for (int r = 0; r < 16; r++) acc[r] += sm[r * 256 + k] * w;
    }
    const float bias = b2[tid];
    #pragma unroll
    for (int r = 0; r < 16; r++)
        g_catep[(size_t)(bbase + r) * 256 + tid] = acc[r] + bias;
}

// ---------------------------------------------------------------------------
// Main fused kernel: one CTA per batch.
//  P1: seq fp32 -> bf16 hi/lo split in SMEM
//  P2: bf16x3 MMA GEMM (hi*hi + hi*lo + lo*hi), sigmoid + row-sum epilogue
//  P3: mask (dtype-adaptive) + softmax over S
//  P4: attn-weighted pooling from SMEM (x = hi + lo)
// ---------------------------------------------------------------------------
__global__ void __launch_bounds__(256, 1)
hba_main_kernel(const float* __restrict__ seq,
                const void*  __restrict__ maskp,
                const float* __restrict__ W1,
                const float* __restrict__ b1,
                float* __restrict__ out) {
    extern __shared__ unsigned smem[];
    unsigned* sXh    = smem;                         // S_PAD * LDW words
    unsigned* sXl    = sXh + S_PAD * LDW;            // S_PAD * LDW words
    float*    sScore = (float*)(sXl + S_PAD * LDW);  // S_PAD
    float*    sC     = sScore + S_PAD;               // 256
    float*    sRed   = sC + 256;                     // 32

    const int b    = blockIdx.x;
    const int tid  = threadIdx.x;
    const int warp = tid >> 5;
    const int lane = tid & 31;
    const int qr   = lane >> 2;     // groupID 0..7
    const int qc   = lane & 3;      // thread-in-group 0..3

    sC[tid] = g_catep[(size_t)b * 256 + tid] + b1[tid];
    if (tid < S_PAD) sScore[tid] = 0.0f;

    // ---- Phase 1: load + bf16 hi/lo split ----
    {
        const float4* gsrc = (const float4*)(seq + (size_t)b * S_SZ * D_SZ);
        for (int idx = tid; idx < S_PAD * 64; idx += 256) {
            const int r  = idx >> 6;
            const int c4 = idx & 63;
            float4 v = make_float4(0.f, 0.f, 0.f, 0.f);
            if (r < S_SZ) v = gsrc[r * 64 + c4];
            const unsigned h01 = pack_bf2(v.x, v.y);
            const unsigned h23 = pack_bf2(v.z, v.w);
            const unsigned l01 = pack_bf2(v.x - bf_lo(h01), v.y - bf_hi(h01));
            const unsigned l23 = pack_bf2(v.z - bf_lo(h23), v.w - bf_hi(h23));
            sXh[r * LDW + c4 * 2]     = h01;
            sXh[r * LDW + c4 * 2 + 1] = h23;
            sXl[r * LDW + c4 * 2]     = l01;
            sXl[r * LDW + c4 * 2 + 1] = l23;
        }
    }
    __syncthreads();

    // ---- Phase 2: GEMM, warp covers e-cols [32*warp, 32*warp+32), 2 passes of 16 ----
    const int n_base = warp * 32;
    #pragma unroll 1
    for (int p = 0; p < 2; p++) {
        const int n0 = n_base + p * 16;
        float acc[13][2][4];
        #pragma unroll
        for (int mt = 0; mt < 13; mt++)
            #pragma unroll
            for (int t = 0; t < 2; t++)
                #pragma unroll
                for (int i = 0; i < 4; i++) acc[mt][t][i] = 0.0f;

        const float* wra = W1 + (size_t)(n0 + qr) * 256 + 2 * qc;       // n-tile A
        const float* wrb = W1 + (size_t)(n0 + 8 + qr) * 256 + 2 * qc;   // n-tile B

        #pragma unroll 1
        for (int kt = 0; kt < 16; kt++) {
            const int k0 = kt * 16;
            const float2 wA0 = *(const float2*)(wra + k0);
            const float2 wA1 = *(const float2*)(wra + k0 + 8);
            const float2 wB0 = *(const float2*)(wrb + k0);
            const float2 wB1 = *(const float2*)(wrb + k0 + 8);
            const unsigned bhA0 = pack_bf2(wA0.x, wA0.y);
            const unsigned bhA1 = pack_bf2(wA1.x, wA1.y);
            const unsigned bhB0 = pack_bf2(wB0.x, wB0.y);
            const unsigned bhB1 = pack_bf2(wB1.x, wB1.y);
            const unsigned blA0 = pack_bf2(wA0.x - bf_lo(bhA0), wA0.y - bf_hi(bhA0));
            const unsigned blA1 = pack_bf2(wA1.x - bf_lo(bhA1), wA1.y - bf_hi(bhA1));
            const unsigned blB0 = pack_bf2(wB0.x - bf_lo(bhB0), wB0.y - bf_hi(bhB0));
            const unsigned blB1 = pack_bf2(wB1.x - bf_lo(bhB1), wB1.y - bf_hi(bhB1));

            const unsigned* ph = sXh + kt * 8 + qc;
            const unsigned* pl = sXl + kt * 8 + qc;
            #pragma unroll
            for (int mt = 0; mt < 13; mt++) {
                const int r0 = (mt * 16 + qr) * LDW;
                const int r1 = r0 + 8 * LDW;
                const unsigned ah0 = ph[r0],     ah1 = ph[r1];
                const unsigned ah2 = ph[r0 + 4], ah3 = ph[r1 + 4];
                const unsigned al0 = pl[r0],     al1 = pl[r1];
                const unsigned al2 = pl[r0 + 4], al3 = pl[r1 + 4];
                MMA16816(acc[mt][0], ah0, ah1, ah2, ah3, bhA0, bhA1);
                MMA16816(acc[mt][0], ah0, ah1, ah2, ah3, blA0, blA1);
                MMA16816(acc[mt][0], al0, al1, al2, al3, bhA0, bhA1);
                MMA16816(acc[mt][1], ah0, ah1, ah2, ah3, bhB0, bhB1);
                MMA16816(acc[mt][1], ah0, ah1, ah2, ah3, blB0, blB1);
                MMA16816(acc[mt][1], al0, al1, al2, al3, bhB0, bhB1);
            }
        }

        // epilogue: sigmoid + per-row partial sums -> smem atomics
        const float biasA0 = sC[n0 + 2 * qc];
        const float biasA1 = sC[n0 + 2 * qc + 1];
        const float biasB0 = sC[n0 + 8 + 2 * qc];
        const float biasB1 = sC[n0 + 8 + 2 * qc + 1];
        #pragma unroll
        for (int mt = 0; mt < 13; mt++) {
            float v0 = sigf(acc[mt][0][0] + biasA0) + sigf(acc[mt][0][1] + biasA1)
                     + sigf(acc[mt][1][0] + biasB0) + sigf(acc[mt][1][1] + biasB1);
            float v1 = sigf(acc[mt][0][2] + biasA0) + sigf(acc[mt][0][3] + biasA1)
                     + sigf(acc[mt][1][2] + biasB0) + sigf(acc[mt][1][3] + biasB1);
            v0 += __shfl_xor_sync(0xffffffffu, v0, 1);
            v0 += __shfl_xor_sync(0xffffffffu, v0, 2);
            v1 += __shfl_xor_sync(0xffffffffu, v1, 1);
            v1 += __shfl_xor_sync(0xffffffffu, v1, 2);
            if (qc == 0) {
                atomicAdd(&sScore[mt * 16 + qr], v0);
                atomicAdd(&sScore[mt * 16 + qr + 8], v1);
            }
        }
    }
    __syncthreads();

    // ---- Phase 3: mask (dtype-adaptive) + softmax ----
    float sv = -3.4e38f;
    if (tid < S_SZ) {
        const size_t mi = (size_t)b * S_SZ + tid;
        const int mode = g_mask_mode;
        bool mk;
        if (mode == 0)      mk = ((const unsigned char*)maskp)[mi] != 0;
        else if (mode == 1) mk = ((const int*)maskp)[mi] != 0;
        else                mk = ((const float*)maskp)[mi] != 0.0f;
        sv = mk ? -1e9f : sScore[tid];
    }

    float m = sv;
    #pragma unroll
    for (int o = 16; o > 0; o >>= 1) m = fmaxf(m, __shfl_xor_sync(0xffffffffu, m, o));
    if (lane == 0) sRed[warp] = m;
    __syncthreads();
    if (warp == 0) {
        float t = (lane < 8) ? sRed[lane] : -3.4e38f;
        #pragma unroll
        for (int o = 16; o > 0; o >>= 1) t = fmaxf(t, __shfl_xor_sync(0xffffffffu, t, o));
        if (lane == 0) sRed[16] = t;
    }
    __syncthreads();
    m = sRed[16];

    const float ev = (tid < S_SZ) ? __expf(sv - m) : 0.0f;
    float l = ev;
    #pragma unroll
    for (int o = 16; o > 0; o >>= 1) l += __shfl_xor_sync(0xffffffffu, l, o);
    if (lane == 0) sRed[warp] = l;
    __syncthreads();
    if (warp == 0) {
        float u = (lane < 8) ? sRed[lane] : 0.0f;
        #pragma unroll
        for (int o = 16; o > 0; o >>= 1) u += __shfl_xor_sync(0xffffffffu, u, o);
        if (lane == 0) sRed[17] = u;
    }
    if (tid < S_SZ) sScore[tid] = ev;
    __syncthreads();
    const float inv = 1.0f / sRed[17];

    // ---- Phase 4: weighted pooling from SMEM (x = hi + lo) ----
    const int wi = tid >> 1;
    const bool hh = tid & 1;
    float accd = 0.0f;
    #pragma unroll 4
    for (int s = 0; s < S_SZ; s++) {
        const float a = sScore[s];
        const unsigned wh = sXh[s * LDW + wi];
        const unsigned wl = sXl[s * LDW + wi];
        const float x = (hh ? bf_hi(wh) : bf_lo(wh)) + (hh ? bf_hi(wl) : bf_lo(wl));
        accd += a * x;
    }
    out[(size_t)b * 256 + tid] = accd * inv;
}

// ---------------------------------------------------------------------------

#define SMEM_BYTES ((2 * S_PAD * LDW + S_PAD + 256 + 32) * (int)sizeof(unsigned))

extern "C" void kernel_launch(void* const* d_in, const int* in_sizes, int n_in,
                              void* d_out, int out_size) {
    const float* cate = (const float*)d_in[0];
    const float* seq  = (const float*)d_in[1];
    const void*  mask = d_in[2];
    const float* W1   = (const float*)d_in[3];
    const float* b1   = (const float*)d_in[4];
    const float* W2   = (const float*)d_in[5];
    const float* b2   = (const float*)d_in[6];
    float*       out  = (float*)d_out;

    cudaFuncSetAttribute(hba_main_kernel,
                         cudaFuncAttributeMaxDynamicSharedMemorySize, SMEM_BYTES);

    detect_mask_kernel<<<1, 32>>>((const unsigned*)mask);
    catep_kernel<<<BATCH / 16, 256>>>(cate, W2, b2);
    hba_main_kernel<<<BATCH, 256, SMEM_BYTES>>>(seq, mask, W1, b1, out);
}

// round 3
// speedup vs baseline: 1.0075x; 1.0075x over previous
#include <cuda_runtime.h>

#define BATCH 4096
#define S_SZ  200
#define S_PAD 208           // 13 m-tiles of 16
#define D_SZ  256
#define LDW   132           // words per row (128 data + 4 pad) -> conflict-free frags

__device__ float g_catep[BATCH * D_SZ];
__device__ int   g_mask_mode;   // 0 = uint8, 1 = int32, 2 = float32

__device__ __forceinline__ unsigned pack_bf2(float lo, float hi) {
    unsigned r;
    asm("cvt.rn.bf16x2.f32 %0, %1, %2;" : "=r"(r) : "f"(hi), "f"(lo));
    return r;
}
__device__ __forceinline__ float bf_lo(unsigned w) { return __uint_as_float(w << 16); }
__device__ __forceinline__ float bf_hi(unsigned w) { return __uint_as_float(w & 0xFFFF0000u); }
__device__ __forceinline__ float sigf(float x) { return 1.0f / (1.0f + __expf(-x)); }

#define MMA16816(d, a0, a1, a2, a3, b0, b1)                                   \
    asm volatile("mma.sync.aligned.m16n8k16.row.col.f32.bf16.bf16.f32 "       \
                 "{%0,%1,%2,%3}, {%4,%5,%6,%7}, {%8,%9}, {%0,%1,%2,%3};"      \
                 : "+f"(d[0]), "+f"(d[1]), "+f"(d[2]), "+f"(d[3])             \
                 : "r"(a0), "r"(a1), "r"(a2), "r"(a3), "r"(b0), "r"(b1))

// ---------------------------------------------------------------------------
// Mask dtype detection: bool may arrive as u8, i32 or f32. Deterministic.
// ---------------------------------------------------------------------------
__global__ void detect_mask_kernel(const unsigned* __restrict__ mw) {
    if (threadIdx.x == 0) {
        int mode = 1;                                // default: int32 (words 0/1)
        for (int i = 0; i < 512; i++) {
            unsigned v = mw[i];
            if (v == 0x3F800000u) { mode = 2; break; }          // float 1.0f
            if ((v & 0xFFFFFF00u) != 0u) { mode = 0; break; }   // bytes 1..3 set -> u8
        }
        g_mask_mode = mode;
    }
}

// ---------------------------------------------------------------------------
// cate_p[b,e] = dot(cate[b,:], W2[e,:]) + b2[e]   (fp32 exact)
// ---------------------------------------------------------------------------
__global__ void catep_kernel(const float* __restrict__ cate,
                             const float* __restrict__ W2,
                             const float* __restrict__ b2) {
    __shared__ float sm[16 * 256];
    const int bbase = blockIdx.x * 16;
    const int tid = threadIdx.x;

    #pragma unroll
    for (int i = 0; i < 16; i++)
        sm[i * 256 + tid] = cate[(size_t)(bbase + i) * 256 + tid];
    __syncthreads();

    float acc[16];
    #pragma unroll
    for (int r = 0; r < 16; r++) acc[r] = 0.0f;

    const float* w2row = W2 + (size_t)tid * 256;
    #pragma unroll 4
    for (int k = 0; k < 256; k++) {
        const float w = w2row[k];
        #pragma unroll
        for (int r = 0; r < 16; r++) acc[r] += sm[r * 256 + k] * w;
    }
    const float bias = b2[tid];
    #pragma unroll
    for (int r = 0; r < 16; r++)
        g_catep[(size_t)(bbase + r) * 256 + tid] = acc[r] + bias;
}

// ---------------------------------------------------------------------------
// Main fused kernel: one CTA per batch.
//  P1: seq fp32 -> bf16 hi/lo split in SMEM
//  P2: bf16x3 MMA GEMM (hi*hi + hi*lo + lo*hi), sigmoid + row-sum epilogue
//  P3: mask (dtype-adaptive) + softmax over S
//  P4: attn-weighted pooling from SMEM (x = hi + lo)
// ---------------------------------------------------------------------------
__global__ void __launch_bounds__(256, 1)
hba_main_kernel(const float* __restrict__ seq,
                const void*  __restrict__ maskp,
                const float* __restrict__ W1,
                const float* __restrict__ b1,
                float* __restrict__ out) {
    extern __shared__ unsigned smem[];
    unsigned* sXh    = smem;                         // S_PAD * LDW words
    unsigned* sXl    = sXh + S_PAD * LDW;            // S_PAD * LDW words
    float*    sScore = (float*)(sXl + S_PAD * LDW);  // S_PAD
    float*    sC     = sScore + S_PAD;               // 256
    float*    sRed   = sC + 256;                     // 32

    const int b    = blockIdx.x;
    const int tid  = threadIdx.x;
    const int warp = tid >> 5;
    const int lane = tid & 31;
    const int qr   = lane >> 2;     // groupID 0..7
    const int qc   = lane & 3;      // thread-in-group 0..3

    sC[tid] = g_catep[(size_t)b * 256 + tid] + b1[tid];
    if (tid < S_PAD) sScore[tid] = 0.0f;

    // ---- Phase 1: load + bf16 hi/lo split ----
    {
        const float4* gsrc = (const float4*)(seq + (size_t)b * S_SZ * D_SZ);
        for (int idx = tid; idx < S_PAD * 64; idx += 256) {
            const int r  = idx >> 6;
            const int c4 = idx & 63;
            float4 v = make_float4(0.f, 0.f, 0.f, 0.f);
            if (r < S_SZ) v = gsrc[r * 64 + c4];
            const unsigned h01 = pack_bf2(v.x, v.y);
            const unsigned h23 = pack_bf2(v.z, v.w);
            const unsigned l01 = pack_bf2(v.x - bf_lo(h01), v.y - bf_hi(h01));
            const unsigned l23 = pack_bf2(v.z - bf_lo(h23), v.w - bf_hi(h23));
            sXh[r * LDW + c4 * 2]     = h01;
            sXh[r * LDW + c4 * 2 + 1] = h23;
            sXl[r * LDW + c4 * 2]     = l01;
            sXl[r * LDW + c4 * 2 + 1] = l23;
        }
    }
    __syncthreads();

    // ---- Phase 2: GEMM, warp covers e-cols [32*warp, 32*warp+32), 2 passes of 16 ----
    const int n_base = warp * 32;
    #pragma unroll 1
    for (int p = 0; p < 2; p++) {
        const int n0 = n_base + p * 16;
        float acc[13][2][4];
        #pragma unroll
        for (int mt = 0; mt < 13; mt++)
            #pragma unroll
            for (int t = 0; t < 2; t++)
                #pragma unroll
                for (int i = 0; i < 4; i++) acc[mt][t][i] = 0.0f;

        const float* wra = W1 + (size_t)(n0 + qr) * 256 + 2 * qc;       // n-tile A
        const float* wrb = W1 + (size_t)(n0 + 8 + qr) * 256 + 2 * qc;   // n-tile B

        #pragma unroll 1
        for (int kt = 0; kt < 16; kt++) {
            const int k0 = kt * 16;
            const float2 wA0 = *(const float2*)(wra + k0);
            const float2 wA1 = *(const float2*)(wra + k0 + 8);
            const float2 wB0 = *(const float2*)(wrb + k0);
            const float2 wB1 = *(const float2*)(wrb + k0 + 8);
            const unsigned bhA0 = pack_bf2(wA0.x, wA0.y);
            const unsigned bhA1 = pack_bf2(wA1.x, wA1.y);
            const unsigned bhB0 = pack_bf2(wB0.x, wB0.y);
            const unsigned bhB1 = pack_bf2(wB1.x, wB1.y);
            const unsigned blA0 = pack_bf2(wA0.x - bf_lo(bhA0), wA0.y - bf_hi(bhA0));
            const unsigned blA1 = pack_bf2(wA1.x - bf_lo(bhA1), wA1.y - bf_hi(bhA1));
            const unsigned blB0 = pack_bf2(wB0.x - bf_lo(bhB0), wB0.y - bf_hi(bhB0));
            const unsigned blB1 = pack_bf2(wB1.x - bf_lo(bhB1), wB1.y - bf_hi(bhB1));

            const unsigned* ph = sXh + kt * 8 + qc;
            const unsigned* pl = sXl + kt * 8 + qc;
            #pragma unroll
            for (int mt = 0; mt < 13; mt++) {
                const int r0 = (mt * 16 + qr) * LDW;
                const int r1 = r0 + 8 * LDW;
                const unsigned ah0 = ph[r0],     ah1 = ph[r1];
                const unsigned ah2 = ph[r0 + 4], ah3 = ph[r1 + 4];
                const unsigned al0 = pl[r0],     al1 = pl[r1];
                const unsigned al2 = pl[r0 + 4], al3 = pl[r1 + 4];
                MMA16816(acc[mt][0], ah0, ah1, ah2, ah3, bhA0, bhA1);
                MMA16816(acc[mt][0], ah0, ah1, ah2, ah3, blA0, blA1);
                MMA16816(acc[mt][0], al0, al1, al2, al3, bhA0, bhA1);
                MMA16816(acc[mt][1], ah0, ah1, ah2, ah3, bhB0, bhB1);
                MMA16816(acc[mt][1], ah0, ah1, ah2, ah3, blB0, blB1);
                MMA16816(acc[mt][1], al0, al1, al2, al3, bhB0, bhB1);
            }
        }

        // epilogue: sigmoid + per-row partial sums -> smem atomics
        const float biasA0 = sC[n0 + 2 * qc];
        const float biasA1 = sC[n0 + 2 * qc + 1];
        const float biasB0 = sC[n0 + 8 + 2 * qc];
        const float biasB1 = sC[n0 + 8 + 2 * qc + 1];
        #pragma unroll
        for (int mt = 0; mt < 13; mt++) {
            float v0 = sigf(acc[mt][0][0] + biasA0) + sigf(acc[mt][0][1] + biasA1)
                     + sigf(acc[mt][1][0] + biasB0) + sigf(acc[mt][1][1] + biasB1);
            float v1 = sigf(acc[mt][0][2] + biasA0) + sigf(acc[mt][0][3] + biasA1)
                     + sigf(acc[mt][1][2] + biasB0) + sigf(acc[mt][1][3] + biasB1);
            v0 += __shfl_xor_sync(0xffffffffu, v0, 1);
            v0 += __shfl_xor_sync(0xffffffffu, v0, 2);
            v1 += __shfl_xor_sync(0xffffffffu, v1, 1);
            v1 += __shfl_xor_sync(0xffffffffu, v1, 2);
            if (qc == 0) {
                atomicAdd(&sScore[mt * 16 + qr], v0);
                atomicAdd(&sScore[mt * 16 + qr + 8], v1);
            }
        }
    }
    __syncthreads();

    // ---- Phase 3: mask (dtype-adaptive) + softmax ----
    float sv = -3.4e38f;
    if (tid < S_SZ) {
        const size_t mi = (size_t)b * S_SZ + tid;
        const int mode = g_mask_mode;
        bool mk;
        if (mode == 0)      mk = ((const unsigned char*)maskp)[mi] != 0;
        else if (mode == 1) mk = ((const int*)maskp)[mi] != 0;
        else                mk = ((const float*)maskp)[mi] != 0.0f;
        sv = mk ? -1e9f : sScore[tid];
    }

    float m = sv;
    #pragma unroll
    for (int o = 16; o > 0; o >>= 1) m = fmaxf(m, __shfl_xor_sync(0xffffffffu, m, o));
    if (lane == 0) sRed[warp] = m;
    __syncthreads();
    if (warp == 0) {
        float t = (lane < 8) ? sRed[lane] : -3.4e38f;
        #pragma unroll
        for (int o = 16; o > 0; o >>= 1) t = fmaxf(t, __shfl_xor_sync(0xffffffffu, t, o));
        if (lane == 0) sRed[16] = t;
    }
    __syncthreads();
    m = sRed[16];

    const float ev = (tid < S_SZ) ? __expf(sv - m) : 0.0f;
    float l = ev;
    #pragma unroll
    for (int o = 16; o > 0; o >>= 1) l += __shfl_xor_sync(0xffffffffu, l, o);
    if (lane == 0) sRed[warp] = l;
    __syncthreads();
    if (warp == 0) {
        float u = (lane < 8) ? sRed[lane] : 0.0f;
        #pragma unroll
        for (int o = 16; o > 0; o >>= 1) u += __shfl_xor_sync(0xffffffffu, u, o);
        if (lane == 0) sRed[17] = u;
    }
    if (tid < S_SZ) sScore[tid] = ev;
    __syncthreads();
    const float inv = 1.0f / sRed[17];

    // ---- Phase 4: weighted pooling from SMEM (x = hi + lo) ----
    const int wi = tid >> 1;
    const bool hh = tid & 1;
    float accd = 0.0f;
    #pragma unroll 4
    for (int s = 0; s < S_SZ; s++) {
        const float a = sScore[s];
        const unsigned wh = sXh[s * LDW + wi];
        const unsigned wl = sXl[s * LDW + wi];
        const float x = (hh ? bf_hi(wh) : bf_lo(wh)) + (hh ? bf_hi(wl) : bf_lo(wl));
        accd += a * x;
    }
    out[(size_t)b * 256 + tid] = accd * inv;
}

// ---------------------------------------------------------------------------

#define SMEM_BYTES ((2 * S_PAD * LDW + S_PAD + 256 + 32) * (int)sizeof(unsigned))

extern "C" void kernel_launch(void* const* d_in, const int* in_sizes, int n_in,
                              void* d_out, int out_size) {
    const float* cate = (const float*)d_in[0];
    const float* seq  = (const float*)d_in[1];
    const void*  mask = d_in[2];
    const float* W1   = (const float*)d_in[3];
    const float* b1   = (const float*)d_in[4];
    const float* W2   = (const float*)d_in[5];
    const float* b2   = (const float*)d_in[6];
    float*       out  = (float*)d_out;

    cudaFuncSetAttribute(hba_main_kernel,
                         cudaFuncAttributeMaxDynamicSharedMemorySize, SMEM_BYTES);

    detect_mask_kernel<<<1, 32>>>((const unsigned*)mask);
    catep_kernel<<<BATCH / 16, 256>>>(cate, W2, b2);
    hba_main_kernel<<<BATCH, 256, SMEM_BYTES>>>(seq, mask, W1, b1, out);
}

// round 5
// speedup vs baseline: 1.2727x; 1.2632x over previous
#include <cuda_runtime.h>
#include <cstdint>

#define BATCH 4096
#define S_SZ  200
#define D_SZ  256

// ---- main-kernel dynamic SMEM word map ----
#define XH_W     0          // 13*16*32*4 = 26624 words: X_hi fragments
#define XL_W     26624      // X_lo fragments
#define SC_W     53248      // 256 f32 combined bias
#define SCORE_W  53504      // 208 f32
#define SRED_W   53712      // 32 f32
#define SMEM_WORDS 53744
#define SMEM_BYTES (SMEM_WORDS * 4)

__device__ float g_catep[BATCH * D_SZ];
__device__ int   g_mask_mode;                 // 0=u8, 1=i32, 2=f32
__device__ uint4 g_w1pk[32 * 16 * 32];        // 256 KB packed W1 fragments

__device__ __forceinline__ unsigned pack_bf2(float lo, float hi) {
    unsigned r;
    asm("cvt.rn.bf16x2.f32 %0, %1, %2;" : "=r"(r) : "f"(hi), "f"(lo));
    return r;
}
__device__ __forceinline__ float bf_lo(unsigned w) { return __uint_as_float(w << 16); }
__device__ __forceinline__ float bf_hi(unsigned w) { return __uint_as_float(w & 0xFFFF0000u); }
__device__ __forceinline__ float sigf(float x) { return __fdividef(1.0f, 1.0f + __expf(-x)); }

#define MMA16816(d, a0, a1, a2, a3, b0, b1)                                   \
    asm volatile("mma.sync.aligned.m16n8k16.row.col.f32.bf16.bf16.f32 "       \
                 "{%0,%1,%2,%3}, {%4,%5,%6,%7}, {%8,%9}, {%0,%1,%2,%3};"      \
                 : "+f"(d[0]), "+f"(d[1]), "+f"(d[2]), "+f"(d[3])             \
                 : "r"(a0), "r"(a1), "r"(a2), "r"(a3), "r"(b0), "r"(b1))

// ---------------------------------------------------------------------------
// Prep kernel (one launch): blocks 0..255 = catep GEMM, 256 = W1 fragment
// packing, 257 = mask dtype detection.
// ---------------------------------------------------------------------------
__global__ void prep_kernel(const float* __restrict__ cate,
                            const float* __restrict__ W2,
                            const float* __restrict__ b2,
                            const float* __restrict__ W1,
                            const unsigned* __restrict__ mw) {
    __shared__ float sm[16 * 256];
    __shared__ int   fl[2];
    const int blk = blockIdx.x, tid = threadIdx.x;

    if (blk < 256) {
        // cate_p[b,e] = dot(cate[b,:], W2[e,:]) + b2[e]  (fp32 exact)
        const int bbase = blk * 16;
        #pragma unroll
        for (int i = 0; i < 16; i++)
            sm[i * 256 + tid] = cate[(size_t)(bbase + i) * 256 + tid];
        __syncthreads();

        float acc[16];
        #pragma unroll
        for (int r = 0; r < 16; r++) acc[r] = 0.0f;
        const float* w2row = W2 + (size_t)tid * 256;
        #pragma unroll 4
        for (int k = 0; k < 256; k++) {
            const float w = w2row[k];
            #pragma unroll
            for (int r = 0; r < 16; r++) acc[r] += sm[r * 256 + k] * w;
        }
        const float bias = b2[tid];
        #pragma unroll
        for (int r = 0; r < 16; r++)
            g_catep[(size_t)(bbase + r) * 256 + tid] = acc[r] + bias;
    } else if (blk == 256) {
        // W1 -> per-lane packed bf16 hi/lo fragments.
        // entry e = (ntg*16 + kt)*32 + lane ; lane = qr*4 + qc
        for (int e = tid; e < 32 * 16 * 32; e += 256) {
            const int ntg = e >> 9, kt = (e >> 5) & 15, lane = e & 31;
            const int qr = lane >> 2, qc = lane & 3;
            const float* src = W1 + (size_t)(ntg * 8 + qr) * 256 + kt * 16 + 2 * qc;
            const float w0 = src[0], w1v = src[1], w8 = src[8], w9 = src[9];
            const unsigned bh0 = pack_bf2(w0, w1v);
            const unsigned bh1 = pack_bf2(w8, w9);
            const unsigned bl0 = pack_bf2(w0 - bf_lo(bh0), w1v - bf_hi(bh0));
            const unsigned bl1 = pack_bf2(w8 - bf_lo(bh1), w9 - bf_hi(bh1));
            g_w1pk[e] = make_uint4(bh0, bh1, bl0, bl1);
        }
    } else {
        // mask dtype detection (bool may arrive as u8 / i32 / f32)
        if (tid == 0) { fl[0] = 0; fl[1] = 0; }
        __syncthreads();
        int lF = 0, lU = 0;
        for (int i = tid; i < 4096; i += 256) {
            const unsigned v = mw[i];
            if (v == 0x3F800000u) lF = 1;
            if (v & 0xFFFFFF00u)  lU = 1;
        }
        if (lF) fl[0] = 1;
        if (lU) fl[1] = 1;
        __syncthreads();
        if (tid == 0) g_mask_mode = fl[0] ? 2 : (fl[1] ? 0 : 1);
    }
}

// ---------------------------------------------------------------------------
// Main fused kernel: one CTA (256 thr) per batch.
//  P1: seq fp32 -> bf16 hi/lo split, stored in MMA-fragment order
//  P2: bf16x3 GEMM (Xh.Wh + Xh.Wl + Xl.Wh) with LDS.128 A / LDG.128 W frags
//  P3: mask + softmax
//  P4: attn pooling from fragment-layout SMEM (x = hi + lo)
// ---------------------------------------------------------------------------
__global__ void __launch_bounds__(256, 1)
hba_main_kernel(const float* __restrict__ seq,
                const void*  __restrict__ maskp,
                const float* __restrict__ b1,
                float* __restrict__ out) {
    extern __shared__ unsigned sw[];
    const int b = blockIdx.x, tid = threadIdx.x;
    const int warp = tid >> 5, lane = tid & 31;
    const int qr = lane >> 2, qc = lane & 3;

    float* sC     = (float*)(sw + SC_W);
    float* sScore = (float*)(sw + SCORE_W);
    float* sRed   = (float*)(sw + SRED_W);

    sC[tid] = g_catep[(size_t)b * 256 + tid] + b1[tid];
    if (tid < 208) sScore[tid] = 0.0f;
    // zero mt=12 pad block (rows 192..207; 192..199 overwritten below)
    for (int i = tid; i < 2048; i += 256) {
        sw[XH_W + 24576 + i] = 0u;
        sw[XL_W + 24576 + i] = 0u;
    }
    __syncthreads();

    // ---- P1: load + split into fragment order ----
    // word(s,d-pair cp): widx = mt*2048 + kt*128 + qr*16 + qc*4 + h2*2 + h1
    {
        const float4* gsrc = (const float4*)(seq + (size_t)b * S_SZ * D_SZ);
        for (int idx = tid; idx < S_SZ * 64; idx += 256) {
            const int r = idx >> 6, c4 = idx & 63;
            const float4 v = gsrc[idx];
            const unsigned h01 = pack_bf2(v.x, v.y);
            const unsigned h23 = pack_bf2(v.z, v.w);
            const unsigned l01 = pack_bf2(v.x - bf_lo(h01), v.y - bf_hi(h01));
            const unsigned l23 = pack_bf2(v.z - bf_lo(h23), v.w - bf_hi(h23));
            const int cp = 2 * c4, rr = cp & 7;
            const int r16 = r & 15;
            const int widx = (r >> 4) * 2048 + (cp >> 3) * 128
                           + (r16 & 7) * 16 + (rr & 3) * 4 + (rr >> 2) * 2 + (r16 >> 3);
            sw[XH_W + widx]     = h01;
            sw[XH_W + widx + 4] = h23;
            sw[XL_W + widx]     = l01;
            sw[XL_W + widx + 4] = l23;
        }
    }
    __syncthreads();

    // ---- P2: GEMM, warp covers n-cols [32*warp, 32*warp+32), 2 passes of 16 ----
    #pragma unroll 1
    for (int p = 0; p < 2; p++) {
        const int n0  = warp * 32 + p * 16;
        const int ntA = n0 >> 3;
        float acc[13][2][4];
        #pragma unroll
        for (int mt = 0; mt < 13; mt++)
            #pragma unroll
            for (int t = 0; t < 2; t++)
                #pragma unroll
                for (int i = 0; i < 4; i++) acc[mt][t][i] = 0.0f;

        const uint4* wpA = g_w1pk + (size_t)(ntA * 16) * 32 + lane;
        const uint4* wpB = g_w1pk + (size_t)((ntA + 1) * 16) * 32 + lane;

        #pragma unroll 4
        for (int kt = 0; kt < 16; kt++) {
            const uint4 wA = wpA[kt * 32];
            const uint4 wB = wpB[kt * 32];
            const unsigned abase = kt * 128 + lane * 4;
            #pragma unroll
            for (int mt = 0; mt < 13; mt++) {
                const uint4 ah = *(const uint4*)(sw + XH_W + mt * 2048 + abase);
                const uint4 al = *(const uint4*)(sw + XL_W + mt * 2048 + abase);
                MMA16816(acc[mt][0], ah.x, ah.y, ah.z, ah.w, wA.x, wA.y);
                MMA16816(acc[mt][0], ah.x, ah.y, ah.z, ah.w, wA.z, wA.w);
                MMA16816(acc[mt][0], al.x, al.y, al.z, al.w, wA.x, wA.y);
                MMA16816(acc[mt][1], ah.x, ah.y, ah.z, ah.w, wB.x, wB.y);
                MMA16816(acc[mt][1], ah.x, ah.y, ah.z, ah.w, wB.z, wB.w);
                MMA16816(acc[mt][1], al.x, al.y, al.z, al.w, wB.x, wB.y);
            }
        }

        // epilogue: sigmoid + per-row partial sums -> smem atomics
        const float bA0 = sC[n0 + 2 * qc],     bA1 = sC[n0 + 2 * qc + 1];
        const float bB0 = sC[n0 + 8 + 2 * qc], bB1 = sC[n0 + 8 + 2 * qc + 1];
        #pragma unroll
        for (int mt = 0; mt < 13; mt++) {
            float v0 = sigf(acc[mt][0][0] + bA0) + sigf(acc[mt][0][1] + bA1)
                     + sigf(acc[mt][1][0] + bB0) + sigf(acc[mt][1][1] + bB1);
            float v1 = sigf(acc[mt][0][2] + bA0) + sigf(acc[mt][0][3] + bA1)
                     + sigf(acc[mt][1][2] + bB0) + sigf(acc[mt][1][3] + bB1);
            v0 += __shfl_xor_sync(0xffffffffu, v0, 1);
            v0 += __shfl_xor_sync(0xffffffffu, v0, 2);
            v1 += __shfl_xor_sync(0xffffffffu, v1, 1);
            v1 += __shfl_xor_sync(0xffffffffu, v1, 2);
            if (qc == 0) {
                atomicAdd(&sScore[mt * 16 + qr], v0);
                atomicAdd(&sScore[mt * 16 + qr + 8], v1);
            }
        }
    }
    __syncthreads();

    // ---- P3: mask (dtype-adaptive) + softmax over S ----
    float sv = -3.4e38f;
    if (tid < S_SZ) {
        const size_t mi = (size_t)b * S_SZ + tid;
        const int mode = g_mask_mode;
        bool mk;
        if (mode == 0)      mk = ((const unsigned char*)maskp)[mi] != 0;
        else if (mode == 1) mk = ((const int*)maskp)[mi] != 0;
        else                mk = ((const float*)maskp)[mi] != 0.0f;
        sv = mk ? -1e9f : sScore[tid];
    }

    float m = sv;
    #pragma unroll
    for (int o = 16; o > 0; o >>= 1) m = fmaxf(m, __shfl_xor_sync(0xffffffffu, m, o));
    if (lane == 0) sRed[warp] = m;
    __syncthreads();
    if (warp == 0) {
        float t = (lane < 8) ? sRed[lane] : -3.4e38f;
        #pragma unroll
        for (int o = 16; o > 0; o >>= 1) t = fmaxf(t, __shfl_xor_sync(0xffffffffu, t, o));
        if (lane == 0) sRed[16] = t;
    }
    __syncthreads();
    m = sRed[16];

    const float ev = (tid < S_SZ) ? __expf(sv - m) : 0.0f;
    float l = ev;
    #pragma unroll
    for (int o = 16; o > 0; o >>= 1) l += __shfl_xor_sync(0xffffffffu, l, o);
    if (lane == 0) sRed[warp] = l;
    __syncthreads();
    if (warp == 0) {
        float u = (lane < 8) ? sRed[lane] : 0.0f;
        #pragma unroll
        for (int o = 16; o > 0; o >>= 1) u += __shfl_xor_sync(0xffffffffu, u, o);
        if (lane == 0) sRed[17] = u;
    }
    if (tid < S_SZ) sScore[tid] = ev;
    __syncthreads();
    const float inv = 1.0f / sRed[17];

    // ---- P4: pooling from fragment layout (x = hi + lo) ----
    {
        const int cp = tid >> 1, hl = tid & 1;
        const int Cd = (cp >> 3) * 128 + (cp & 3) * 4 + ((cp & 7) >> 2) * 2;
        float accd = 0.0f;
        #pragma unroll 4
        for (int s = 0; s < S_SZ; s++) {
            const int fs = (s >> 4) * 2048 + (s & 7) * 16 + ((s & 15) >> 3);
            const unsigned wh = sw[XH_W + Cd + fs];
            const unsigned wl = sw[XL_W + Cd + fs];
            const float x = (hl ? bf_hi(wh) : bf_lo(wh)) + (hl ? bf_hi(wl) : bf_lo(wl));
            accd += sScore[s] * x;
        }
        out[(size_t)b * 256 + tid] = accd * inv;
    }
}

// ---------------------------------------------------------------------------
extern "C" void kernel_launch(void* const* d_in, const int* in_sizes, int n_in,
                              void* d_out, int out_size) {
    const float* cate = (const float*)d_in[0];
    const float* seq  = (const float*)d_in[1];
    const void*  mask = d_in[2];
    const float* W1   = (const float*)d_in[3];
    const float* b1   = (const float*)d_in[4];
    const float* W2   = (const float*)d_in[5];
    const float* b2   = (const float*)d_in[6];
    float*       out  = (float*)d_out;

    cudaFuncSetAttribute(hba_main_kernel,
                         cudaFuncAttributeMaxDynamicSharedMemorySize, SMEM_BYTES);

    prep_kernel<<<258, 256>>>(cate, W2, b2, W1, (const unsigned*)mask);
    hba_main_kernel<<<BATCH, 256, SMEM_BYTES>>>(seq, mask, b1, out);
}